// round 7
// baseline (speedup 1.0000x reference)
#include <cuda_runtime.h>

#define BB 32
#define SS 2048
#define DD 1024
#define KATT 10
#define D4 (DD / 4)        // 256 float4 per hidden row
#define GRID 1024
#define NT 128

// Scratch (no allocation allowed)
__device__ float g_partial[GRID * DD];         // 4 MB: one partial row per block
__device__ float g_vraw[BB * DD];
__device__ float g_vn[BB * DD];
__device__ float g_corr[BB * DD];

// Barrier state (self-resetting per launch; graph-replay safe)
__device__ int g_cnt1 = 0;
__device__ int g_cnt2 = 0;
__device__ volatile unsigned g_gen1 = 0;
__device__ volatile unsigned g_gen2 = 0;

__global__ void __launch_bounds__(NT, 8) fused_kernel(const float* __restrict__ h,
                                                      const float* __restrict__ att,
                                                      float* __restrict__ out) {
    const int tid = threadIdx.x;
    const int lane = tid & 31;
    const int wid = tid >> 5;

    __shared__ unsigned s_g1, s_g2;
    __shared__ int s_arr;
    __shared__ float s_s1[KATT];     // 1/max(|a|,1e-8)
    __shared__ float s_cs[KATT];     // cosine scale
    __shared__ float s_alpha[BB];
    __shared__ int   s_best[BB];

    if (tid == 0) { s_g1 = g_gen1; s_g2 = g_gen2; }

    const float4* h4 = (const float4*)h;
    float4* gp4 = (float4*)g_partial;
    float4* vr4 = (float4*)g_vraw;

    // ---------------- phase 1: partial sums (block = b*32+c, 64 rows) --------
    {
        const float4* p = h4 + ((size_t)blockIdx.x << 14);  // 64 rows * 256 f4
        float4 a0 = make_float4(0.f, 0.f, 0.f, 0.f);
        float4 a1 = make_float4(0.f, 0.f, 0.f, 0.f);
#pragma unroll 4
        for (int s = 0; s < 64; ++s) {
            float4 u = __ldcs(p + s * D4 + tid);
            float4 w = __ldcs(p + s * D4 + tid + 128);
            a0.x += u.x; a0.y += u.y; a0.z += u.z; a0.w += u.w;
            a1.x += w.x; a1.y += w.y; a1.z += w.z; a1.w += w.w;
        }
        gp4[blockIdx.x * D4 + tid] = a0;
        gp4[blockIdx.x * D4 + tid + 128] = a1;
    }

    // ---------------- barrier 1 ----------------------------------------------
    __syncthreads();
    if (tid == 0) {
        __threadfence();
        s_arr = atomicAdd(&g_cnt1, 1);
    }
    __syncthreads();
    if (s_arr == GRID - 1 && tid == 0) {
        g_cnt1 = 0;
        __threadfence();
        g_gen1 = s_g1 + 1;
    }
    if (tid == 0) { while (g_gen1 == s_g1) __nanosleep(128); }
    __syncthreads();
    __threadfence();

    // ---------------- phase 1.5: blocks 0..31 reduce -> v_raw ----------------
    if (blockIdx.x < BB) {
        int b = blockIdx.x;
#pragma unroll
        for (int half = 0; half < 2; ++half) {
            int col = tid + half * 128;
            float4 s = make_float4(0.f, 0.f, 0.f, 0.f);
#pragma unroll
            for (int c = 0; c < 32; ++c) {
                float4 v = gp4[(b * 32 + c) * D4 + col];
                s.x += v.x; s.y += v.y; s.z += v.z; s.w += v.w;
            }
            const float inv = 1.0f / (float)SS;
            s.x *= inv; s.y *= inv; s.z *= inv; s.w *= inv;
            vr4[b * D4 + col] = s;
        }
    }

    // ---------------- barrier 2; last arriver runs all small math ------------
    __syncthreads();
    if (tid == 0) {
        __threadfence();
        s_arr = atomicAdd(&g_cnt2, 1);
    }
    __syncthreads();
    if (s_arr == GRID - 1) {
        __threadfence();
        // --- attractor scales: warp w handles k = w, w+4, w+8 ---
        for (int k = wid; k < KATT; k += 4) {
            float s = 0.f;
            for (int j = lane; j < DD; j += 32) {
                float a = att[k * DD + j];
                s += a * a;
            }
#pragma unroll
            for (int o = 16; o; o >>= 1) s += __shfl_xor_sync(0xffffffff, s, o);
            if (lane == 0) {
                float n1 = sqrtf(s);
                float s1 = 1.0f / fmaxf(n1, 1e-8f);
                float n2 = n1 * s1;
                s_s1[k] = s1;
                s_cs[k] = s1 / fmaxf(n2, 1e-12f);
            }
        }
        // --- whitening: thread covers cols tid and tid+128 (float4) ---
        {
            float4* vn4 = (float4*)g_vn;
#pragma unroll
            for (int half = 0; half < 2; ++half) {
                int col = tid + half * 128;
                float4 sum = make_float4(0.f, 0.f, 0.f, 0.f);
#pragma unroll
                for (int b = 0; b < BB; ++b) {
                    float4 v = vr4[b * D4 + col];
                    sum.x += v.x; sum.y += v.y; sum.z += v.z; sum.w += v.w;
                }
                const float invB = 1.0f / (float)BB;
                float4 mean = make_float4(sum.x * invB, sum.y * invB,
                                          sum.z * invB, sum.w * invB);
                float4 s2 = make_float4(0.f, 0.f, 0.f, 0.f);
#pragma unroll
                for (int b = 0; b < BB; ++b) {
                    float4 v = vr4[b * D4 + col];
                    float tx = v.x - mean.x, ty = v.y - mean.y;
                    float tz = v.z - mean.z, tw = v.w - mean.w;
                    s2.x += tx * tx; s2.y += ty * ty;
                    s2.z += tz * tz; s2.w += tw * tw;
                }
                float4 inv;
                inv.x = 1.0f / sqrtf(s2.x * invB + 1e-8f);
                inv.y = 1.0f / sqrtf(s2.y * invB + 1e-8f);
                inv.z = 1.0f / sqrtf(s2.z * invB + 1e-8f);
                inv.w = 1.0f / sqrtf(s2.w * invB + 1e-8f);
#pragma unroll
                for (int b = 0; b < BB; ++b) {
                    float4 v = vr4[b * D4 + col];
                    float4 o;
                    o.x = (v.x - mean.x) * inv.x;
                    o.y = (v.y - mean.y) * inv.y;
                    o.z = (v.z - mean.z) * inv.z;
                    o.w = (v.w - mean.w) * inv.w;
                    vn4[b * D4 + col] = o;
                }
            }
        }
        __syncthreads();
        // --- cosine + argmax: warp w handles rows w, w+4, ..., w+28 ---
        for (int t = 0; t < 8; ++t) {
            int b = wid + t * 4;
            float vnr[32];
#pragma unroll
            for (int j = 0; j < 32; ++j) vnr[j] = g_vn[b * DD + lane + 32 * j];
            float best = -1e30f;
            int bi = 0;
            for (int k = 0; k < KATT; ++k) {
                float p = 0.f;
#pragma unroll
                for (int j = 0; j < 32; ++j) p += vnr[j] * att[k * DD + lane + 32 * j];
#pragma unroll
                for (int o = 16; o; o >>= 1) p += __shfl_xor_sync(0xffffffff, p, o);
                float cosv = p * s_cs[k];
                if (cosv > best) { best = cosv; bi = k; }  // strict > == jnp.argmax
            }
            if (lane == 0) {
                s_alpha[b] = 0.3f * (1.0f - best);
                s_best[b] = bi;
            }
        }
        __syncthreads();
        // --- correction = v_norm + alpha*clip(closest - v_norm) - v_raw ---
        {
            const float4* vn4 = (const float4*)g_vn;
            const float4* at4 = (const float4*)att;
            float4* co4 = (float4*)g_corr;
#pragma unroll
            for (int half = 0; half < 2; ++half) {
                int col = tid + half * 128;
#pragma unroll
                for (int b = 0; b < BB; ++b) {
                    float4 vn = vn4[b * D4 + col];
                    float4 vr = vr4[b * D4 + col];
                    int k = s_best[b];
                    float s1 = s_s1[k];
                    float al = s_alpha[b];
                    float4 a = at4[k * D4 + col];
                    float4 o;
                    float dx = fminf(fmaxf(a.x * s1 - vn.x, -0.5f), 0.5f);
                    float dy = fminf(fmaxf(a.y * s1 - vn.y, -0.5f), 0.5f);
                    float dz = fminf(fmaxf(a.z * s1 - vn.z, -0.5f), 0.5f);
                    float dw = fminf(fmaxf(a.w * s1 - vn.w, -0.5f), 0.5f);
                    o.x = vn.x + al * dx - vr.x;
                    o.y = vn.y + al * dy - vr.y;
                    o.z = vn.z + al * dz - vr.z;
                    o.w = vn.w + al * dw - vr.w;
                    co4[b * D4 + col] = o;
                }
            }
        }
        __syncthreads();
        if (tid == 0) {
            g_cnt2 = 0;
            __threadfence();
            g_gen2 = s_g2 + 1;
        }
    }
    if (tid == 0) { while (g_gen2 == s_g2) __nanosleep(128); }
    __syncthreads();
    __threadfence();

    // ---------------- phase 3: out = h + corr[b][:] broadcast ----------------
    {
        float4* o4 = (float4*)out;
        const unsigned base0 = blockIdx.x * 16384u;   // 16384 f4 per block
        const unsigned b = base0 >> 19;               // uniform per block
        const float4* co4 = (const float4*)g_corr;
        float4 c0 = co4[(b << 8) + tid];              // cols tid, tid+128 cached
        float4 c1 = co4[(b << 8) + tid + 128];
#pragma unroll 2
        for (int it = 0; it < 32; ++it) {
            unsigned i0 = base0 + it * 512u + tid;
            float4 v0 = __ldcs(&h4[i0]);
            float4 v1 = __ldcs(&h4[i0 + 128]);
            float4 v2 = __ldcs(&h4[i0 + 256]);
            float4 v3 = __ldcs(&h4[i0 + 384]);
            v0.x += c0.x; v0.y += c0.y; v0.z += c0.z; v0.w += c0.w;
            v1.x += c1.x; v1.y += c1.y; v1.z += c1.z; v1.w += c1.w;
            v2.x += c0.x; v2.y += c0.y; v2.z += c0.z; v2.w += c0.w;
            v3.x += c1.x; v3.y += c1.y; v3.z += c1.z; v3.w += c1.w;
            __stcs(&o4[i0], v0);
            __stcs(&o4[i0 + 128], v1);
            __stcs(&o4[i0 + 256], v2);
            __stcs(&o4[i0 + 384], v3);
        }
    }
}

extern "C" void kernel_launch(void* const* d_in, const int* in_sizes, int n_in,
                              void* d_out, int out_size) {
    const float* hidden = (const float*)d_in[0];   // [32, 2048, 1024] f32
    const float* att    = (const float*)d_in[1];   // [10, 1024] f32
    float* out = (float*)d_out;
    fused_kernel<<<GRID, NT>>>(hidden, att, out);
}

// round 8
// speedup vs baseline: 1.3805x; 1.3805x over previous
#include <cuda_runtime.h>

#define BB 32
#define SS 2048
#define DD 1024
#define KATT 10
#define CHUNKS 32
#define ROWS_PER_CHUNK (SS / CHUNKS)   // 64
#define D4 (DD / 4)                    // 256 float4 per row

// Scratch (no allocation allowed)
__device__ float g_partial[BB * CHUNKS * DD];  // 4 MB
__device__ float g_vraw[BB * DD];
__device__ float g_vn[BB * DD];
__device__ float g_corr[BB * DD];
__device__ float g_s1[KATT];    // 1/max(|a|,1e-8)
__device__ float g_cs[KATT];    // cosine scale: s1 / max(|a|*s1, 1e-12)

// ---------------------------------------------------------------------------
// k1: blocks 0..1023 -> partial sums over sequence chunks (block = b*32+c,
//     sums 64 rows). Blocks 1024..1033 -> attractor norm scales (block per k).
// ---------------------------------------------------------------------------
__global__ void __launch_bounds__(256) k1_partial(const float* __restrict__ h,
                                                  const float* __restrict__ att) {
    if (blockIdx.x < BB * CHUNKS) {
        const float4* h4 = (const float4*)h;
        const float4* p = h4 + ((size_t)blockIdx.x << 14) + threadIdx.x; // 64*256 f4/block
        float4 acc = make_float4(0.f, 0.f, 0.f, 0.f);
#pragma unroll 16
        for (int s = 0; s < ROWS_PER_CHUNK; ++s) {
            float4 v = __ldcs(&p[s * D4]);
            acc.x += v.x; acc.y += v.y; acc.z += v.z; acc.w += v.w;
        }
        ((float4*)g_partial)[blockIdx.x * D4 + threadIdx.x] = acc;
    } else {
        // attractor scales: one block per k, 256 threads, 1 float4 each
        int k = blockIdx.x - BB * CHUNKS;
        int t = threadIdx.x;
        __shared__ float s_part[8];
        float4 a = ((const float4*)att)[k * D4 + t];
        float p = a.x * a.x + a.y * a.y + a.z * a.z + a.w * a.w;
#pragma unroll
        for (int o = 16; o; o >>= 1) p += __shfl_xor_sync(0xffffffff, p, o);
        if ((t & 31) == 0) s_part[t >> 5] = p;
        __syncthreads();
        if (t == 0) {
            float s = 0.f;
#pragma unroll
            for (int w = 0; w < 8; ++w) s += s_part[w];
            float n1 = sqrtf(s);
            float s1 = 1.0f / fmaxf(n1, 1e-8f);
            float n2 = n1 * s1;
            g_s1[k] = s1;
            g_cs[k] = s1 / fmaxf(n2, 1e-12f);
        }
    }
}

// ---------------------------------------------------------------------------
// k1b: reduce the 32 chunk-partials -> v_raw (mean over S). 32 blocks x 256.
// ---------------------------------------------------------------------------
__global__ void __launch_bounds__(256) k1b_reduce() {
    int b = blockIdx.x;
    int t = threadIdx.x;
    const float4* p4 = (const float4*)g_partial;
    float4 acc = make_float4(0.f, 0.f, 0.f, 0.f);
#pragma unroll
    for (int c = 0; c < CHUNKS; ++c) {
        float4 v = p4[(b * CHUNKS + c) * D4 + t];
        acc.x += v.x; acc.y += v.y; acc.z += v.z; acc.w += v.w;
    }
    const float inv = 1.0f / (float)SS;
    acc.x *= inv; acc.y *= inv; acc.z *= inv; acc.w *= inv;
    ((float4*)g_vraw)[b * D4 + t] = acc;
}

// ---------------------------------------------------------------------------
// k2a: whitening, parallel over dims. 32 blocks x 256 threads; thread owns
// float4 column (blockIdx*256 + tid). Single-pass sum/sumsq, then normalize.
// ---------------------------------------------------------------------------
__global__ void __launch_bounds__(256) k2a_whiten() {
    int col = blockIdx.x * 256 + threadIdx.x;   // f4 col in [0, 8192) -> only 8192/256=32 blocks... col < D4 slabs per batch handled below
    // Actually: total f4 cols per batch row = 256; whitening is per scalar dim.
    // Layout: vr4[b * D4 + c] for c in [0, 256). We need 8192 (b,c) writes but
    // stats are per-c over b. 32 blocks x 256 threads = 8192 threads; map
    // thread -> c = global_tid % 256?? Simpler: 1 block per 8 c-cols is
    // overkill; use: only blocks 0..0? -- Use: c = col & 255, and have each
    // group of 256 threads (one block) handle ALL b for its 256 c columns:
    // block x handles c = tid, batch rows [x*... no: stats need all b.
    // FINAL mapping: block x, thread t: c = t (each block redundantly computes
    // stats for its own b-slice write range). We split the WRITE over blocks:
    // block x writes batch row x (32 blocks, 32 rows), each recomputing
    // per-c stats from L2-hot g_vraw (cheap: 32 f4 loads/thread).
    (void)col;
    const float4* vr4 = (const float4*)g_vraw;
    float4* vn4 = (float4*)g_vn;
    int t = threadIdx.x;
    float4 sum = make_float4(0.f, 0.f, 0.f, 0.f);
    float4 sq = make_float4(0.f, 0.f, 0.f, 0.f);
#pragma unroll
    for (int b = 0; b < BB; ++b) {
        float4 v = vr4[b * D4 + t];
        sum.x += v.x; sum.y += v.y; sum.z += v.z; sum.w += v.w;
        sq.x += v.x * v.x; sq.y += v.y * v.y; sq.z += v.z * v.z; sq.w += v.w * v.w;
    }
    const float invB = 1.0f / (float)BB;
    float4 mean = make_float4(sum.x * invB, sum.y * invB, sum.z * invB, sum.w * invB);
    float4 inv;
    inv.x = 1.0f / sqrtf(sq.x * invB - mean.x * mean.x + 1e-8f);
    inv.y = 1.0f / sqrtf(sq.y * invB - mean.y * mean.y + 1e-8f);
    inv.z = 1.0f / sqrtf(sq.z * invB - mean.z * mean.z + 1e-8f);
    inv.w = 1.0f / sqrtf(sq.w * invB - mean.w * mean.w + 1e-8f);
    // write only this block's batch row
    int b = blockIdx.x;
    float4 v = vr4[b * D4 + t];
    float4 o;
    o.x = (v.x - mean.x) * inv.x;
    o.y = (v.y - mean.y) * inv.y;
    o.z = (v.z - mean.z) * inv.z;
    o.w = (v.w - mean.w) * inv.w;
    vn4[b * D4 + t] = o;
}

// ---------------------------------------------------------------------------
// k2b: per-batch cosine/argmax/correction. 32 blocks (one per b) x 256 thr.
// ---------------------------------------------------------------------------
__global__ void __launch_bounds__(256) k2b_snap(const float* __restrict__ att) {
    __shared__ float s_part[8];
    __shared__ float s_alpha;
    __shared__ int s_best;
    int b = blockIdx.x;
    int t = threadIdx.x;
    const float4* vn4 = (const float4*)g_vn;
    const float4* vr4 = (const float4*)g_vraw;
    const float4* at4 = (const float4*)att;

    float4 vn = vn4[b * D4 + t];
    float best = -1e30f;
    int bi = 0;
    for (int k = 0; k < KATT; ++k) {
        float4 a = at4[k * D4 + t];
        float p = vn.x * a.x + vn.y * a.y + vn.z * a.z + vn.w * a.w;
#pragma unroll
        for (int o = 16; o; o >>= 1) p += __shfl_xor_sync(0xffffffff, p, o);
        if ((t & 31) == 0) s_part[t >> 5] = p;
        __syncthreads();
        // every thread computes the same fixed-order sum (deterministic)
        float dot = 0.f;
#pragma unroll
        for (int w = 0; w < 8; ++w) dot += s_part[w];
        float cosv = dot * g_cs[k];
        if (cosv > best) { best = cosv; bi = k; }   // strict > == first-max
        __syncthreads();
    }
    if (t == 0) { s_alpha = 0.3f * (1.0f - best); s_best = bi; }
    __syncthreads();

    int k = s_best;
    float s1 = g_s1[k];
    float al = s_alpha;
    float4 a = at4[k * D4 + t];
    float4 vr = vr4[b * D4 + t];
    float4 o;
    float dx = fminf(fmaxf(a.x * s1 - vn.x, -0.5f), 0.5f);
    float dy = fminf(fmaxf(a.y * s1 - vn.y, -0.5f), 0.5f);
    float dz = fminf(fmaxf(a.z * s1 - vn.z, -0.5f), 0.5f);
    float dw = fminf(fmaxf(a.w * s1 - vn.w, -0.5f), 0.5f);
    o.x = vn.x + al * dx - vr.x;
    o.y = vn.y + al * dy - vr.y;
    o.z = vn.z + al * dz - vr.z;
    o.w = vn.w + al * dw - vr.w;
    ((float4*)g_corr)[b * D4 + t] = o;
}

// ---------------------------------------------------------------------------
// k3: out[b][s][d] = h[b][s][d] + corr[b][d], 8 float4 per thread.
// Block covers 2048 contiguous float4 (32 KB); 2048 | 2^19 -> b uniform per
// block; all 8 offsets == tid (mod 256) -> ONE corr load per thread.
// grid = 8192 blocks x 256 threads.
// ---------------------------------------------------------------------------
__global__ void __launch_bounds__(256) k3_apply(const float* __restrict__ h,
                                                float* __restrict__ out) {
    const float4* h4 = (const float4*)h;
    float4* o4 = (float4*)out;
    unsigned base = blockIdx.x * 2048u + threadIdx.x;
    float4 v0 = __ldcs(&h4[base]);
    float4 v1 = __ldcs(&h4[base + 256]);
    float4 v2 = __ldcs(&h4[base + 512]);
    float4 v3 = __ldcs(&h4[base + 768]);
    float4 v4 = __ldcs(&h4[base + 1024]);
    float4 v5 = __ldcs(&h4[base + 1280]);
    float4 v6 = __ldcs(&h4[base + 1536]);
    float4 v7 = __ldcs(&h4[base + 1792]);
    unsigned b = base >> 19;                 // uniform per block
    float4 c = ((const float4*)g_corr)[(b << 8) + threadIdx.x];
    v0.x += c.x; v0.y += c.y; v0.z += c.z; v0.w += c.w;
    v1.x += c.x; v1.y += c.y; v1.z += c.z; v1.w += c.w;
    v2.x += c.x; v2.y += c.y; v2.z += c.z; v2.w += c.w;
    v3.x += c.x; v3.y += c.y; v3.z += c.z; v3.w += c.w;
    v4.x += c.x; v4.y += c.y; v4.z += c.z; v4.w += c.w;
    v5.x += c.x; v5.y += c.y; v5.z += c.z; v5.w += c.w;
    v6.x += c.x; v6.y += c.y; v6.z += c.z; v6.w += c.w;
    v7.x += c.x; v7.y += c.y; v7.z += c.z; v7.w += c.w;
    __stcs(&o4[base], v0);
    __stcs(&o4[base + 256], v1);
    __stcs(&o4[base + 512], v2);
    __stcs(&o4[base + 768], v3);
    __stcs(&o4[base + 1024], v4);
    __stcs(&o4[base + 1280], v5);
    __stcs(&o4[base + 1536], v6);
    __stcs(&o4[base + 1792], v7);
}

// ---------------------------------------------------------------------------
extern "C" void kernel_launch(void* const* d_in, const int* in_sizes, int n_in,
                              void* d_out, int out_size) {
    const float* hidden = (const float*)d_in[0];   // [32, 2048, 1024] f32
    const float* att    = (const float*)d_in[1];   // [10, 1024] f32
    float* out = (float*)d_out;

    k1_partial<<<BB * CHUNKS + KATT, 256>>>(hidden, att);
    k1b_reduce<<<BB, 256>>>();
    k2a_whiten<<<BB, 256>>>();
    k2b_snap<<<BB, 256>>>(att);
    const unsigned total4 = (unsigned)BB * SS * D4;       // 16,777,216 float4
    k3_apply<<<total4 / 2048, 256>>>(hidden, out);        // 8192 blocks
}

// round 9
// speedup vs baseline: 1.4012x; 1.0150x over previous
#include <cuda_runtime.h>

#define BB 32
#define SS 2048
#define DD 1024
#define KATT 10
#define CHUNKS 32
#define ROWS_PER_CHUNK (SS / CHUNKS)   // 64
#define D4 (DD / 4)                    // 256 float4 per row

// Scratch (no allocation allowed)
__device__ float g_partial[BB * CHUNKS * DD];  // 4 MB
__device__ float g_vraw[BB * DD];
__device__ float g_corr[BB * DD];
__device__ float g_s1[KATT];    // 1/max(|a|,1e-8)
__device__ float g_cs[KATT];    // cosine scale: s1 / max(|a|*s1, 1e-12)

// kmid barrier state (self-resetting per launch; graph-replay safe)
__device__ int g_cnt = 0;
__device__ volatile unsigned g_gen = 0;

// ---------------------------------------------------------------------------
// k1: blocks 0..1023 -> partial sums over sequence chunks (block = b*32+c,
//     sums 64 rows). Blocks 1024..1033 -> attractor norm scales (block per k).
// ---------------------------------------------------------------------------
__global__ void __launch_bounds__(256) k1_partial(const float* __restrict__ h,
                                                  const float* __restrict__ att) {
    if (blockIdx.x < BB * CHUNKS) {
        const float4* h4 = (const float4*)h;
        const float4* p = h4 + ((size_t)blockIdx.x << 14) + threadIdx.x; // 64*256 f4/block
        float4 acc = make_float4(0.f, 0.f, 0.f, 0.f);
#pragma unroll 16
        for (int s = 0; s < ROWS_PER_CHUNK; ++s) {
            float4 v = __ldcs(&p[s * D4]);
            acc.x += v.x; acc.y += v.y; acc.z += v.z; acc.w += v.w;
        }
        ((float4*)g_partial)[blockIdx.x * D4 + threadIdx.x] = acc;
    } else {
        // attractor scales: one block per k, 256 threads, 1 float4 each
        int k = blockIdx.x - BB * CHUNKS;
        int t = threadIdx.x;
        __shared__ float s_part[8];
        float4 a = ((const float4*)att)[k * D4 + t];
        float p = a.x * a.x + a.y * a.y + a.z * a.z + a.w * a.w;
#pragma unroll
        for (int o = 16; o; o >>= 1) p += __shfl_xor_sync(0xffffffff, p, o);
        if ((t & 31) == 0) s_part[t >> 5] = p;
        __syncthreads();
        if (t == 0) {
            float s = 0.f;
#pragma unroll
            for (int w = 0; w < 8; ++w) s += s_part[w];
            float n1 = sqrtf(s);
            float s1 = 1.0f / fmaxf(n1, 1e-8f);
            float n2 = n1 * s1;
            g_s1[k] = s1;
            g_cs[k] = s1 / fmaxf(n2, 1e-12f);
        }
    }
}

// ---------------------------------------------------------------------------
// kmid: fused k1b + whitening + snap. 32 blocks (one per batch row) x 256 thr.
//   1. reduce 32 chunk-partials -> vraw[b] (kept in registers too)
//   2. 32-block generation barrier
//   3. whitening stats over L2-hot vraw (redundant per block, deterministic)
//   4. 10 cosines: per-thread partials first, 10 shfl trees, ONE sync,
//      uniform fixed-order final sums + argmax in every thread
//   5. corr[b] written
// ---------------------------------------------------------------------------
__global__ void __launch_bounds__(256) kmid(const float* __restrict__ att) {
    __shared__ float s_part[KATT][8];
    __shared__ float s_cs[KATT];
    __shared__ float s_s1[KATT];
    __shared__ unsigned s_gen;

    const int b = blockIdx.x;
    const int t = threadIdx.x;
    const int lane = t & 31;
    const int wid = t >> 5;
    const float4* gp4 = (const float4*)g_partial;
    float4* vr4 = (float4*)g_vraw;
    const float4* at4 = (const float4*)att;

    if (t == 0) s_gen = g_gen;
    if (t >= 32 && t < 32 + KATT) s_cs[t - 32] = g_cs[t - 32];
    if (t >= 64 && t < 64 + KATT) s_s1[t - 64] = g_s1[t - 64];

    // --- 1. reduce partials -> vraw[b] ---
    float4 acc = make_float4(0.f, 0.f, 0.f, 0.f);
#pragma unroll
    for (int c = 0; c < CHUNKS; ++c) {
        float4 v = gp4[(b * CHUNKS + c) * D4 + t];
        acc.x += v.x; acc.y += v.y; acc.z += v.z; acc.w += v.w;
    }
    {
        const float inv = 1.0f / (float)SS;
        acc.x *= inv; acc.y *= inv; acc.z *= inv; acc.w *= inv;
    }
    vr4[b * D4 + t] = acc;

    // --- 2. grid barrier over 32 blocks ---
    __syncthreads();
    if (t == 0) {
        __threadfence();
        int a = atomicAdd(&g_cnt, 1);
        if (a == BB - 1) {
            g_cnt = 0;
            __threadfence();
            g_gen = s_gen + 1;
        }
        while (g_gen == s_gen) { }
    }
    __syncthreads();
    __threadfence();

    // --- 3. whitening stats (identical fixed-order in every block) ---
    float4 sum = make_float4(0.f, 0.f, 0.f, 0.f);
    float4 sq = make_float4(0.f, 0.f, 0.f, 0.f);
#pragma unroll
    for (int bb = 0; bb < BB; ++bb) {
        float4 v = vr4[bb * D4 + t];
        sum.x += v.x; sum.y += v.y; sum.z += v.z; sum.w += v.w;
        sq.x += v.x * v.x; sq.y += v.y * v.y; sq.z += v.z * v.z; sq.w += v.w * v.w;
    }
    const float invB = 1.0f / (float)BB;
    float4 mean = make_float4(sum.x * invB, sum.y * invB, sum.z * invB, sum.w * invB);
    float4 inv;
    inv.x = 1.0f / sqrtf(sq.x * invB - mean.x * mean.x + 1e-8f);
    inv.y = 1.0f / sqrtf(sq.y * invB - mean.y * mean.y + 1e-8f);
    inv.z = 1.0f / sqrtf(sq.z * invB - mean.z * mean.z + 1e-8f);
    inv.w = 1.0f / sqrtf(sq.w * invB - mean.w * mean.w + 1e-8f);
    float4 vn;
    vn.x = (acc.x - mean.x) * inv.x;
    vn.y = (acc.y - mean.y) * inv.y;
    vn.z = (acc.z - mean.z) * inv.z;
    vn.w = (acc.w - mean.w) * inv.w;

    // --- 4. cosines: partial dots, 10 shfl trees, one sync, uniform argmax ---
    float p[KATT];
#pragma unroll
    for (int k = 0; k < KATT; ++k) {
        float4 a = at4[k * D4 + t];
        p[k] = vn.x * a.x + vn.y * a.y + vn.z * a.z + vn.w * a.w;
    }
#pragma unroll
    for (int k = 0; k < KATT; ++k) {
#pragma unroll
        for (int o = 16; o; o >>= 1) p[k] += __shfl_xor_sync(0xffffffff, p[k], o);
        if (lane == 0) s_part[k][wid] = p[k];
    }
    __syncthreads();

    float best = -1e30f;
    int bi = 0;
#pragma unroll
    for (int k = 0; k < KATT; ++k) {
        float dot = 0.f;
#pragma unroll
        for (int w = 0; w < 8; ++w) dot += s_part[k][w];   // fixed order: deterministic
        float cosv = dot * s_cs[k];
        if (cosv > best) { best = cosv; bi = k; }          // strict > == jnp first-max
    }

    // --- 5. correction = v_norm + alpha*clip(closest - v_norm) - v_raw ---
    {
        float s1 = s_s1[bi];
        float al = 0.3f * (1.0f - best);
        float4 a = at4[bi * D4 + t];
        float4 o;
        float dx = fminf(fmaxf(a.x * s1 - vn.x, -0.5f), 0.5f);
        float dy = fminf(fmaxf(a.y * s1 - vn.y, -0.5f), 0.5f);
        float dz = fminf(fmaxf(a.z * s1 - vn.z, -0.5f), 0.5f);
        float dw = fminf(fmaxf(a.w * s1 - vn.w, -0.5f), 0.5f);
        o.x = vn.x + al * dx - acc.x;
        o.y = vn.y + al * dy - acc.y;
        o.z = vn.z + al * dz - acc.z;
        o.w = vn.w + al * dw - acc.w;
        ((float4*)g_corr)[b * D4 + t] = o;
    }
}

// ---------------------------------------------------------------------------
// k3: out[b][s][d] = h[b][s][d] + corr[b][d], 8 float4 per thread.
// Block covers 2048 contiguous float4 (32 KB); 2048 | 2^19 -> b uniform per
// block; all 8 offsets == tid (mod 256) -> ONE corr load per thread.
// grid = 8192 blocks x 256 threads.
// ---------------------------------------------------------------------------
__global__ void __launch_bounds__(256) k3_apply(const float* __restrict__ h,
                                                float* __restrict__ out) {
    const float4* h4 = (const float4*)h;
    float4* o4 = (float4*)out;
    unsigned base = blockIdx.x * 2048u + threadIdx.x;
    float4 v0 = __ldcs(&h4[base]);
    float4 v1 = __ldcs(&h4[base + 256]);
    float4 v2 = __ldcs(&h4[base + 512]);
    float4 v3 = __ldcs(&h4[base + 768]);
    float4 v4 = __ldcs(&h4[base + 1024]);
    float4 v5 = __ldcs(&h4[base + 1280]);
    float4 v6 = __ldcs(&h4[base + 1536]);
    float4 v7 = __ldcs(&h4[base + 1792]);
    unsigned b = base >> 19;                 // uniform per block
    float4 c = ((const float4*)g_corr)[(b << 8) + threadIdx.x];
    v0.x += c.x; v0.y += c.y; v0.z += c.z; v0.w += c.w;
    v1.x += c.x; v1.y += c.y; v1.z += c.z; v1.w += c.w;
    v2.x += c.x; v2.y += c.y; v2.z += c.z; v2.w += c.w;
    v3.x += c.x; v3.y += c.y; v3.z += c.z; v3.w += c.w;
    v4.x += c.x; v4.y += c.y; v4.z += c.z; v4.w += c.w;
    v5.x += c.x; v5.y += c.y; v5.z += c.z; v5.w += c.w;
    v6.x += c.x; v6.y += c.y; v6.z += c.z; v6.w += c.w;
    v7.x += c.x; v7.y += c.y; v7.z += c.z; v7.w += c.w;
    __stcs(&o4[base], v0);
    __stcs(&o4[base + 256], v1);
    __stcs(&o4[base + 512], v2);
    __stcs(&o4[base + 768], v3);
    __stcs(&o4[base + 1024], v4);
    __stcs(&o4[base + 1280], v5);
    __stcs(&o4[base + 1536], v6);
    __stcs(&o4[base + 1792], v7);
}

// ---------------------------------------------------------------------------
extern "C" void kernel_launch(void* const* d_in, const int* in_sizes, int n_in,
                              void* d_out, int out_size) {
    const float* hidden = (const float*)d_in[0];   // [32, 2048, 1024] f32
    const float* att    = (const float*)d_in[1];   // [10, 1024] f32
    float* out = (float*)d_out;

    k1_partial<<<BB * CHUNKS + KATT, 256>>>(hidden, att);
    kmid<<<BB, 256>>>(att);
    const unsigned total4 = (unsigned)BB * SS * D4;       // 16,777,216 float4
    k3_apply<<<total4 / 2048, 256>>>(hidden, out);        // 8192 blocks
}